// round 2
// baseline (speedup 1.0000x reference)
#include <cuda_runtime.h>
#include <cuda_bf16.h>
#include <cstdint>

// ---------------------------------------------------------------------------
// AdaptiveEMAModel: embed -> FFN -> LayerNorm -> k-projection ->
// sequential gated delta-rule scan -> readout -> two projections.
// All fp32 (fire gate is discontinuous; low precision flips gates).
// Uses packed fma.rn.f32x2 (SASS FFMA2) for 2x fp32 throughput on sm_103a.
// ---------------------------------------------------------------------------

typedef unsigned long long u64t;

__device__ __forceinline__ u64t pk2(float lo, float hi) {
    u64t r;
    asm("mov.b64 %0, {%1, %2};" : "=l"(r) : "f"(lo), "f"(hi));
    return r;
}
__device__ __forceinline__ void fma2(u64t& d, u64t a, u64t b) {
    asm("fma.rn.f32x2 %0, %1, %2, %0;" : "+l"(d) : "l"(a), "l"(b));
}
__device__ __forceinline__ float2 upk(u64t v) {
    float2 f;
    asm("mov.b64 {%0, %1}, %2;" : "=f"(f.x), "=f"(f.y) : "l"(v));
    return f;
}
__device__ __forceinline__ float hsum(u64t v) {
    float2 f = upk(v);
    return f.x + f.y;
}

// ------------------------- constants ---------------------------------------
#define Bn   64
#define Ln   2048
#define Hn   128
#define H2n  256
#define Vn   32000
#define NTOK (Bn * Ln)          // 131072
#define NTIL (NTOK / 32)        // 4096 tiles of 32 tokens

// ------------------------- global scratch (no allocs allowed) --------------
__device__ __align__(16) float g_y[(size_t)NTOK * H2n];     // 134 MB
__device__ __align__(16) float g_hln[(size_t)NTOK * Hn];    // 67 MB
__device__ __align__(16) float g_kall[(size_t)NTOK * Hn];   // 67 MB
__device__ __align__(16) float g_knorm[NTOK];
__device__ __align__(16) float g_read[Bn * Hn];
__device__ __align__(16) float g_r2[Bn * Hn];
__device__ int g_is64;

// ------------------------- K0: detect seq dtype ----------------------------
// int64 tokens < 32000 => every odd 32-bit word is zero.
__global__ void k0_detect(const unsigned int* __restrict__ sw) {
    int t = threadIdx.x;
    int nz = (sw[2 * t + 1] != 0u) ? 1 : 0;
    nz = __syncthreads_or(nz);
    if (t == 0) g_is64 = nz ? 0 : 1;
}

// ------------------------- K1a: embed gather + FFN layer 1 + relu ----------
// Persistent CTAs. smem: W1 staged (256 x pitch130) + X tile (32 x pitch132).
#define K1A_SMEM ((256 * 130 + 32 * 132) * 4)

__global__ __launch_bounds__(256, 1)
void k1a(const void* __restrict__ seq, const float* __restrict__ ew,
         const float* __restrict__ w1, const float* __restrict__ b1) {
    extern __shared__ float sm[];
    float* W = sm;               // 256 rows x 130
    float* X = sm + 256 * 130;   // 32 rows x 132

    const int tid = threadIdx.x;
    const int lane = tid & 31;
    const int w = tid >> 5;
    const int is64 = g_is64;

    // stage W1 with pitch 130 (conflict-free LDS.64 for strided-row reads)
    for (int i = tid; i < 256 * 64; i += 256) {
        int r = i >> 6, c = i & 63;
        *(float2*)(W + r * 130 + 2 * c) = *(const float2*)(w1 + r * 128 + 2 * c);
    }
    float bb[8];
#pragma unroll
    for (int j = 0; j < 8; ++j) bb[j] = b1[lane + 32 * j];
    __syncthreads();

    for (int tile = blockIdx.x; tile < NTIL; tile += gridDim.x) {
        const long long t0 = (long long)tile * 32;
        // gather embeddings: 32 tokens x 128 floats
        for (int i = tid; i < 32 * 32; i += 256) {
            int tk = i >> 5, q = i & 31;
            long long idx = is64 ? ((const long long*)seq)[t0 + tk]
                                 : (long long)((const int*)seq)[t0 + tk];
            *(float4*)(X + tk * 132 + 4 * q) = *(const float4*)(ew + idx * 128 + 4 * q);
        }
        __syncthreads();

        // GEMM: Y[32 x 256] = relu(X @ W1^T + b1); thread: 4 tokens x 8 outputs
        u64t acc[4][8];
#pragma unroll
        for (int i = 0; i < 4; ++i)
#pragma unroll
            for (int j = 0; j < 8; ++j) acc[i][j] = 0ull;

#pragma unroll 8
        for (int h2 = 0; h2 < 64; ++h2) {
            u64t xv[4], wv[8];
#pragma unroll
            for (int i = 0; i < 4; ++i)
                xv[i] = *(const u64t*)(X + (w * 4 + i) * 132 + 2 * h2);
#pragma unroll
            for (int j = 0; j < 8; ++j)
                wv[j] = *(const u64t*)(W + (lane + 32 * j) * 130 + 2 * h2);
#pragma unroll
            for (int i = 0; i < 4; ++i)
#pragma unroll
                for (int j = 0; j < 8; ++j) fma2(acc[i][j], xv[i], wv[j]);
        }
#pragma unroll
        for (int i = 0; i < 4; ++i)
#pragma unroll
            for (int j = 0; j < 8; ++j) {
                float y = hsum(acc[i][j]) + bb[j];
                g_y[(t0 + w * 4 + i) * H2n + lane + 32 * j] = fmaxf(y, 0.0f);
            }
        __syncthreads();
    }
}

// ------------------------- K1b: FFN layer 2 + residual + LayerNorm ---------
#define K1B_SMEM ((128 * 258 + 32 * 258 + 32 * 132) * 4)

__global__ __launch_bounds__(256, 1)
void k1b(const void* __restrict__ seq, const float* __restrict__ ew,
         const float* __restrict__ w2, const float* __restrict__ b2,
         const float* __restrict__ lng, const float* __restrict__ lnb) {
    extern __shared__ float sm[];
    float* W = sm;                          // 128 x 258
    float* Y = sm + 128 * 258;              // 32 x 258
    float* X = sm + 128 * 258 + 32 * 258;   // 32 x 132

    const int tid = threadIdx.x;
    const int lane = tid & 31;
    const int w = tid >> 5;
    const int is64 = g_is64;

    for (int i = tid; i < 128 * 128; i += 256) {
        int r = i >> 7, c = i & 127;
        *(float2*)(W + r * 258 + 2 * c) = *(const float2*)(w2 + r * 256 + 2 * c);
    }
    float b2r[4], gr[4], br[4];
#pragma unroll
    for (int j = 0; j < 4; ++j) {
        b2r[j] = b2[lane + 32 * j];
        gr[j] = lng[lane + 32 * j];
        br[j] = lnb[lane + 32 * j];
    }
    __syncthreads();

    for (int tile = blockIdx.x; tile < NTIL; tile += gridDim.x) {
        const long long t0 = (long long)tile * 32;
        for (int i = tid; i < 32 * 32; i += 256) {
            int tk = i >> 5, q = i & 31;
            long long idx = is64 ? ((const long long*)seq)[t0 + tk]
                                 : (long long)((const int*)seq)[t0 + tk];
            *(float4*)(X + tk * 132 + 4 * q) = *(const float4*)(ew + idx * 128 + 4 * q);
        }
        for (int i = tid; i < 32 * 128; i += 256) {
            int tk = i >> 7, c = i & 127;
            *(float2*)(Y + tk * 258 + 2 * c) = *(const float2*)(g_y + (t0 + tk) * H2n + 2 * c);
        }
        __syncthreads();

        // x[32 x 128] = h + Y @ W2^T + b2 ; thread: 4 tokens x 4 outputs
        u64t acc[4][4];
#pragma unroll
        for (int i = 0; i < 4; ++i)
#pragma unroll
            for (int j = 0; j < 4; ++j) acc[i][j] = 0ull;

#pragma unroll 8
        for (int o2 = 0; o2 < 128; ++o2) {
            u64t yv[4], wv[4];
#pragma unroll
            for (int i = 0; i < 4; ++i)
                yv[i] = *(const u64t*)(Y + (w * 4 + i) * 258 + 2 * o2);
#pragma unroll
            for (int j = 0; j < 4; ++j)
                wv[j] = *(const u64t*)(W + (lane + 32 * j) * 258 + 2 * o2);
#pragma unroll
            for (int i = 0; i < 4; ++i)
#pragma unroll
                for (int j = 0; j < 4; ++j) fma2(acc[i][j], yv[i], wv[j]);
        }

        float x[4][4];
#pragma unroll
        for (int i = 0; i < 4; ++i)
#pragma unroll
            for (int j = 0; j < 4; ++j)
                x[i][j] = hsum(acc[i][j]) + b2r[j] + X[(w * 4 + i) * 132 + lane + 32 * j];

        // LayerNorm per token (each warp fully owns its 4 tokens)
#pragma unroll
        for (int i = 0; i < 4; ++i) {
            float s = x[i][0] + x[i][1] + x[i][2] + x[i][3];
#pragma unroll
            for (int off = 16; off; off >>= 1) s += __shfl_xor_sync(0xffffffffu, s, off);
            float mu = s * (1.0f / 128.0f);
            float vs = 0.0f;
#pragma unroll
            for (int j = 0; j < 4; ++j) { float dv = x[i][j] - mu; vs += dv * dv; }
#pragma unroll
            for (int off = 16; off; off >>= 1) vs += __shfl_xor_sync(0xffffffffu, vs, off);
            float den = sqrtf(vs * (1.0f / 128.0f) + 1e-5f);
#pragma unroll
            for (int j = 0; j < 4; ++j) {
                float h = (x[i][j] - mu) / den * gr[j] + br[j];
                g_hln[(t0 + w * 4 + i) * Hn + lane + 32 * j] = h;
            }
        }
        __syncthreads();
    }
}

// ------------------------- K1c: k projection -------------------------------
#define K1C_SMEM ((128 * 130 + 32 * 132) * 4)

__global__ __launch_bounds__(256, 1)
void k1c(const float* __restrict__ kpw) {
    extern __shared__ float sm[];
    float* W = sm;               // 128 x 130
    float* X = sm + 128 * 130;   // 32 x 132

    const int tid = threadIdx.x;
    const int lane = tid & 31;
    const int w = tid >> 5;

    for (int i = tid; i < 128 * 64; i += 256) {
        int r = i >> 6, c = i & 63;
        *(float2*)(W + r * 130 + 2 * c) = *(const float2*)(kpw + r * 128 + 2 * c);
    }
    __syncthreads();

    for (int tile = blockIdx.x; tile < NTIL; tile += gridDim.x) {
        const long long t0 = (long long)tile * 32;
        for (int i = tid; i < 32 * 32; i += 256) {
            int tk = i >> 5, q = i & 31;
            *(float4*)(X + tk * 132 + 4 * q) = *(const float4*)(g_hln + (t0 + tk) * Hn + 4 * q);
        }
        __syncthreads();

        u64t acc[4][4];
#pragma unroll
        for (int i = 0; i < 4; ++i)
#pragma unroll
            for (int j = 0; j < 4; ++j) acc[i][j] = 0ull;

#pragma unroll 8
        for (int h2 = 0; h2 < 64; ++h2) {
            u64t xv[4], wv[4];
#pragma unroll
            for (int i = 0; i < 4; ++i)
                xv[i] = *(const u64t*)(X + (w * 4 + i) * 132 + 2 * h2);
#pragma unroll
            for (int j = 0; j < 4; ++j)
                wv[j] = *(const u64t*)(W + (lane + 32 * j) * 130 + 2 * h2);
#pragma unroll
            for (int i = 0; i < 4; ++i)
#pragma unroll
                for (int j = 0; j < 4; ++j) fma2(acc[i][j], xv[i], wv[j]);
        }
#pragma unroll
        for (int i = 0; i < 4; ++i)
#pragma unroll
            for (int j = 0; j < 4; ++j)
                g_kall[(t0 + w * 4 + i) * Hn + lane + 32 * j] = hsum(acc[i][j]);
        __syncthreads();
    }
}

// ------------------------- K1d: precompute ||k|| per token -----------------
__global__ void k1d() {
    int row = blockIdx.x * 8 + (threadIdx.x >> 5);
    int lane = threadIdx.x & 31;
    float4 v = *(const float4*)(g_kall + (size_t)row * Hn + lane * 4);
    float s = v.x * v.x + v.y * v.y + v.z * v.z + v.w * v.w;
#pragma unroll
    for (int off = 16; off; off >>= 1) s += __shfl_xor_sync(0xffffffffu, s, off);
    if (lane == 0) g_knorm[row] = sqrtf(s);
}

// ------------------------- K2: sequential delta-rule scan ------------------
// 64 CTAs (1/batch) x 256 threads. Thread pair (2r, 2r+1) owns M row r
// (each thread 64 columns = 32 f32x2 registers). 2047 steps.
__global__ __launch_bounds__(256, 1)
void k2_scan() {
    const int b = blockIdx.x;
    const int tid = threadIdx.x;
    const int lane = tid & 31;
    const int w = tid >> 5;
    const int row = tid >> 1;
    const int half = tid & 1;
    const float* kb = g_kall + (size_t)b * Ln * Hn;
    const float* nb = g_knorm + b * Ln;

    // kn value for column j lives at kns[buf][68*(j>>6) + (j&63)]:
    // the 68-float half offset puts even/odd-lane broadcast reads on
    // distinct banks (conflict-free LDS.64).
    __shared__ float kns[2][136];
    __shared__ float red[2][8];

    u64t M[32];
#pragma unroll
    for (int c = 0; c < 32; ++c) M[c] = 0ull;

    float kcur = kb[row];
    float ncur = nb[0];

    for (int t = 0; t < Ln - 1; ++t) {
        const int buf = t & 1;
        // prefetch next step (t = 2046 prefetches q = k[2047])
        float knext = kb[(t + 1) * Hn + row];
        float nnext = nb[t + 1];

        if (half == 0) {
            float nm = fmaxf(ncur, 1e-12f);
            kns[buf][68 * (row >> 6) + (row & 63)] = kcur / nm;
        }
        __syncthreads();

        const u64t* knp = (const u64t*)(&kns[buf][68 * half]);
        u64t kr[32];
        u64t a0 = 0ull, a1 = 0ull;
#pragma unroll
        for (int c = 0; c < 32; c += 2) {
            kr[c] = knp[c];
            kr[c + 1] = knp[c + 1];
            fma2(a0, M[c], kr[c]);
            fma2(a1, M[c + 1], kr[c + 1]);
        }
        float vph = hsum(a0) + hsum(a1);
        float vp = vph + __shfl_xor_sync(0xffffffffu, vph, 1);
        float d = kcur - vp;
        float dsq = (half == 0) ? d * d : 0.0f;
#pragma unroll
        for (int off = 16; off; off >>= 1) dsq += __shfl_xor_sync(0xffffffffu, dsq, off);
        if (lane == 0) red[buf][w] = dsq;
        __syncthreads();
        float dd = 0.0f;
#pragma unroll
        for (int i = 0; i < 8; ++i) dd += red[buf][i];

        if (sqrtf(dd) >= 0.4f * ncur) {
            float s = d * (1.0f / 2048.0f);   // (1 - alpha) * d, exact
            u64t s2 = pk2(s, s);
#pragma unroll
            for (int c = 0; c < 32; ++c) fma2(M[c], s2, kr[c]);
        }
        kcur = knext;
        ncur = nnext;
    }

    // read = M @ q (q = raw k at t = L-1, already in kcur)
    if (half == 0) kns[0][68 * (row >> 6) + (row & 63)] = kcur;
    __syncthreads();
    {
        const u64t* knp = (const u64t*)(&kns[0][68 * half]);
        u64t a0 = 0ull, a1 = 0ull;
#pragma unroll
        for (int c = 0; c < 32; c += 2) {
            fma2(a0, M[c], knp[c]);
            fma2(a1, M[c + 1], knp[c + 1]);
        }
        float vph = hsum(a0) + hsum(a1);
        float rd = vph + __shfl_xor_sync(0xffffffffu, vph, 1);
        if (half == 0) g_read[b * Hn + row] = rd;
    }
}

// ------------------------- K2b: r2 = read @ rp_w^T + rp_b ------------------
__global__ void k2b(const float* __restrict__ rpw, const float* __restrict__ rpb) {
    __shared__ __align__(16) float rs[128];
    const int b = blockIdx.x, tid = threadIdx.x;
    rs[tid] = g_read[b * Hn + tid];
    __syncthreads();
    const u64t* rp = (const u64t*)rs;
    u64t acc = 0ull;
#pragma unroll 8
    for (int j2 = 0; j2 < 64; ++j2) {
        u64t wv = *(const u64t*)(rpw + tid * 128 + 2 * j2);
        fma2(acc, rp[j2], wv);
    }
    g_r2[b * Hn + tid] = hsum(acc) + rpb[tid];
}

// ------------------------- K3: out = r2 @ out_w^T + out_b ------------------
#define K3_SMEM ((64 * 128 + 64 * 130) * 4)

__global__ __launch_bounds__(256, 1)
void k3(const float* __restrict__ ow, const float* __restrict__ ob,
        float* __restrict__ out) {
    extern __shared__ float sm[];
    float* r2s = sm;             // 64 x 128
    float* ws = sm + 64 * 128;   // 64 x 130

    const int tid = threadIdx.x;
    const int v0 = blockIdx.x * 64;

    for (int i = tid; i < 64 * 32; i += 256)
        ((float4*)r2s)[i] = ((const float4*)g_r2)[i];
    for (int i = tid; i < 64 * 64; i += 256) {
        int r = i >> 6, c = i & 63;
        *(float2*)(ws + r * 130 + 2 * c) = *(const float2*)(ow + (size_t)(v0 + r) * 128 + 2 * c);
    }
    __syncthreads();

    const int vl = tid & 63;
    const int bg = tid >> 6;
    const float obv = ob[v0 + vl];

#pragma unroll 4
    for (int bi = 0; bi < 16; ++bi) {
        int bb = bg * 16 + bi;
        u64t acc = 0ull;
#pragma unroll 16
        for (int h2 = 0; h2 < 64; ++h2)
            fma2(acc, *(const u64t*)(r2s + bb * 128 + 2 * h2),
                      *(const u64t*)(ws + vl * 130 + 2 * h2));
        out[(size_t)bb * Vn + v0 + vl] = hsum(acc) + obv;
    }
}

// ------------------------- launch ------------------------------------------
extern "C" void kernel_launch(void* const* d_in, const int* in_sizes, int n_in,
                              void* d_out, int out_size) {
    (void)in_sizes; (void)n_in; (void)out_size;
    const void*  seq = d_in[0];
    const float* ew  = (const float*)d_in[1];
    const float* w1  = (const float*)d_in[2];
    const float* b1  = (const float*)d_in[3];
    const float* w2  = (const float*)d_in[4];
    const float* b2  = (const float*)d_in[5];
    const float* lng = (const float*)d_in[6];
    const float* lnb = (const float*)d_in[7];
    const float* kpw = (const float*)d_in[8];
    const float* rpw = (const float*)d_in[9];
    const float* rpb = (const float*)d_in[10];
    const float* ow  = (const float*)d_in[11];
    const float* ob  = (const float*)d_in[12];
    float* out = (float*)d_out;

    cudaFuncSetAttribute(k1a, cudaFuncAttributeMaxDynamicSharedMemorySize, K1A_SMEM);
    cudaFuncSetAttribute(k1b, cudaFuncAttributeMaxDynamicSharedMemorySize, K1B_SMEM);
    cudaFuncSetAttribute(k1c, cudaFuncAttributeMaxDynamicSharedMemorySize, K1C_SMEM);
    cudaFuncSetAttribute(k3,  cudaFuncAttributeMaxDynamicSharedMemorySize, K3_SMEM);

    k0_detect<<<1, 256>>>((const unsigned int*)seq);
    k1a<<<152, 256, K1A_SMEM>>>(seq, ew, w1, b1);
    k1b<<<152, 256, K1B_SMEM>>>(seq, ew, w2, b2, lng, lnb);
    k1c<<<304, 256, K1C_SMEM>>>(kpw);
    k1d<<<NTOK / 8, 256>>>();
    k2_scan<<<Bn, 256>>>();
    k2b<<<Bn, 128>>>(rpw, rpb);
    k3<<<Vn / 64, 256, K3_SMEM>>>(ow, ob, out);
}

// round 3
// speedup vs baseline: 1.1856x; 1.1856x over previous
#include <cuda_runtime.h>
#include <cuda_bf16.h>
#include <cstdint>

// ---------------------------------------------------------------------------
// AdaptiveEMAModel. Key ideas:
//  * k_t is a pure function of the vocab id -> compute FFN/LN/kproj over the
//    32000-row vocab table (4.1x fewer flops), then gather per token.
//  * fp32 everywhere (fire gate is discontinuous), packed fma.rn.f32x2
//    (SASS FFMA2) for 2x fp32 throughput.
//  * Scan: lag-2 lazy update + precomputed adjacent Gram g1[t] = kn_{t-1}.kn_t
//    takes the ||d||^2 block reduction off the critical path.
// ---------------------------------------------------------------------------

typedef unsigned long long u64t;

__device__ __forceinline__ u64t pk2(float lo, float hi) {
    u64t r;
    asm("mov.b64 %0, {%1, %2};" : "=l"(r) : "f"(lo), "f"(hi));
    return r;
}
__device__ __forceinline__ void fma2(u64t& d, u64t a, u64t b) {
    asm("fma.rn.f32x2 %0, %1, %2, %0;" : "+l"(d) : "l"(a), "l"(b));
}
__device__ __forceinline__ float hsum(u64t v) {
    float2 f;
    asm("mov.b64 {%0, %1}, %2;" : "=f"(f.x), "=f"(f.y) : "l"(v));
    return f.x + f.y;
}

#define Bn   64
#define Ln   2048
#define Hn   128
#define H2n  256
#define Vn   32000
#define NTOK (Bn * Ln)

// ------------------------- global scratch ----------------------------------
__device__ __align__(16) float g_y[(size_t)Vn * H2n];      // 32.8 MB
__device__ __align__(16) float g_hln[(size_t)Vn * Hn];     // 16.4 MB
__device__ __align__(16) float g_Kv[(size_t)Vn * Hn];      // raw k per vocab
__device__ __align__(16) float g_KNv[(size_t)Vn * Hn];     // normalized k
__device__ __align__(16) float g_THv[Vn];                  // 0.16*||k||^2
__device__ __align__(16) float g_kall[(size_t)NTOK * Hn];  // per-token raw k
__device__ __align__(16) float g_knall[(size_t)NTOK * Hn]; // per-token kn
__device__ __align__(16) float g_thtok[NTOK];
__device__ __align__(16) float g_g1[NTOK];                 // kn_{t-1}.kn_t
__device__ __align__(16) float g_read[Bn * Hn];
__device__ __align__(16) float g_r2[Bn * Hn];
__device__ int g_is64;

// ------------------------- K0: detect seq dtype ----------------------------
__global__ void k0_detect(const unsigned int* __restrict__ sw) {
    int t = threadIdx.x;
    int nz = (sw[2 * t + 1] != 0u) ? 1 : 0;
    nz = __syncthreads_or(nz);
    if (t == 0) g_is64 = nz ? 0 : 1;
}

// ------------------------- KV1: FFN layer 1 over vocab ---------------------
// Tile = 32 vocab rows. smem: W1 256x132 + X 32x132. 8 warps; warp: token
// group (w&3)*8, output group (w>>2)*4x32. Thread tile 8 tok x 4 out.
#define KV1_SMEM ((256 * 132 + 32 * 132) * 4)

__global__ __launch_bounds__(256, 1)
void kv1(const float* __restrict__ ew,
         const float* __restrict__ w1, const float* __restrict__ b1) {
    extern __shared__ float sm[];
    float* W = sm;                // 256 x 132
    float* X = sm + 256 * 132;    // 32 x 132

    const int tid = threadIdx.x;
    const int lane = tid & 31;
    const int w = tid >> 5;
    const int tg = (w & 3) * 8;
    const int ob = (w >> 2) * 4;

    for (int i = tid; i < 256 * 32; i += 256) {
        int r = i >> 5, c = i & 31;
        *(float4*)(W + r * 132 + 4 * c) = *(const float4*)(w1 + r * 128 + 4 * c);
    }
    float bb[4];
#pragma unroll
    for (int j = 0; j < 4; ++j) bb[j] = b1[lane + 32 * (ob + j)];
    __syncthreads();

    const float4* W4 = (const float4*)W;
    const float4* X4 = (const float4*)X;

    for (int tile = blockIdx.x; tile < Vn / 32; tile += gridDim.x) {
        const int v0 = tile * 32;
        for (int i = tid; i < 32 * 32; i += 256) {
            int tk = i >> 5, q = i & 31;
            *(float4*)(X + tk * 132 + 4 * q) = *(const float4*)(ew + (size_t)(v0 + tk) * 128 + 4 * q);
        }
        __syncthreads();

        u64t acc[8][4];
#pragma unroll
        for (int i = 0; i < 8; ++i)
#pragma unroll
            for (int j = 0; j < 4; ++j) acc[i][j] = 0ull;

#pragma unroll 4
        for (int hh = 0; hh < 32; ++hh) {
            u64t wl[4], wh[4];
#pragma unroll
            for (int j = 0; j < 4; ++j) {
                float4 wq = W4[(lane + 32 * (ob + j)) * 33 + hh];
                wl[j] = pk2(wq.x, wq.y);
                wh[j] = pk2(wq.z, wq.w);
            }
#pragma unroll
            for (int i = 0; i < 8; ++i) {
                float4 xq = X4[(tg + i) * 33 + hh];
                u64t xl = pk2(xq.x, xq.y), xh = pk2(xq.z, xq.w);
#pragma unroll
                for (int j = 0; j < 4; ++j) {
                    fma2(acc[i][j], xl, wl[j]);
                    fma2(acc[i][j], xh, wh[j]);
                }
            }
        }
#pragma unroll
        for (int i = 0; i < 8; ++i)
#pragma unroll
            for (int j = 0; j < 4; ++j) {
                float y = hsum(acc[i][j]) + bb[j];
                g_y[(size_t)(v0 + tg + i) * H2n + lane + 32 * (ob + j)] = fmaxf(y, 0.0f);
            }
        __syncthreads();
    }
}

// ------------------------- KV2: FFN layer 2 + residual + LN over vocab -----
// Tile = 64 vocab rows. smem: W2 128x260 + Y 64x260. Residual read from ew
// in epilogue (no X staging). Warp w: tokens w*8..w*8+7, all 128 outputs.
#define KV2_SMEM ((128 * 260 + 64 * 260) * 4)

__global__ __launch_bounds__(256, 1)
void kv2(const float* __restrict__ ew,
         const float* __restrict__ w2, const float* __restrict__ b2,
         const float* __restrict__ lng, const float* __restrict__ lnb) {
    extern __shared__ float sm[];
    float* W = sm;                // 128 x 260
    float* Y = sm + 128 * 260;    // 64 x 260

    const int tid = threadIdx.x;
    const int lane = tid & 31;
    const int w = tid >> 5;
    const int tg = w * 8;

    for (int i = tid; i < 128 * 64; i += 256) {
        int r = i >> 6, c = i & 63;
        *(float4*)(W + r * 260 + 4 * c) = *(const float4*)(w2 + r * 256 + 4 * c);
    }
    float b2r[4], gr[4], br[4];
#pragma unroll
    for (int j = 0; j < 4; ++j) {
        b2r[j] = b2[lane + 32 * j];
        gr[j] = lng[lane + 32 * j];
        br[j] = lnb[lane + 32 * j];
    }
    __syncthreads();

    const float4* W4 = (const float4*)W;
    const float4* Y4 = (const float4*)Y;

    for (int tile = blockIdx.x; tile < Vn / 64; tile += gridDim.x) {
        const int v0 = tile * 64;
        for (int i = tid; i < 64 * 64; i += 256) {
            int tk = i >> 6, c = i & 63;
            *(float4*)(Y + tk * 260 + 4 * c) = *(const float4*)(g_y + (size_t)(v0 + tk) * H2n + 4 * c);
        }
        __syncthreads();

        u64t acc[8][4];
#pragma unroll
        for (int i = 0; i < 8; ++i)
#pragma unroll
            for (int j = 0; j < 4; ++j) acc[i][j] = 0ull;

#pragma unroll 2
        for (int oo = 0; oo < 64; ++oo) {
            u64t wl[4], wh[4];
#pragma unroll
            for (int j = 0; j < 4; ++j) {
                float4 wq = W4[(lane + 32 * j) * 65 + oo];
                wl[j] = pk2(wq.x, wq.y);
                wh[j] = pk2(wq.z, wq.w);
            }
#pragma unroll
            for (int i = 0; i < 8; ++i) {
                float4 yq = Y4[(tg + i) * 65 + oo];
                u64t yl = pk2(yq.x, yq.y), yh = pk2(yq.z, yq.w);
#pragma unroll
                for (int j = 0; j < 4; ++j) {
                    fma2(acc[i][j], yl, wl[j]);
                    fma2(acc[i][j], yh, wh[j]);
                }
            }
        }

#pragma unroll
        for (int i = 0; i < 8; ++i) {
            const size_t tok = (size_t)(v0 + tg + i);
            float x[4];
#pragma unroll
            for (int j = 0; j < 4; ++j)
                x[j] = hsum(acc[i][j]) + b2r[j] + ew[tok * 128 + lane + 32 * j];
            float s = x[0] + x[1] + x[2] + x[3];
#pragma unroll
            for (int off = 16; off; off >>= 1) s += __shfl_xor_sync(0xffffffffu, s, off);
            float mu = s * (1.0f / 128.0f);
            float vs = 0.0f;
#pragma unroll
            for (int j = 0; j < 4; ++j) { float dv = x[j] - mu; vs += dv * dv; }
#pragma unroll
            for (int off = 16; off; off >>= 1) vs += __shfl_xor_sync(0xffffffffu, vs, off);
            float den = sqrtf(vs * (1.0f / 128.0f) + 1e-5f);
#pragma unroll
            for (int j = 0; j < 4; ++j)
                g_hln[tok * Hn + lane + 32 * j] = (x[j] - mu) / den * gr[j] + br[j];
        }
        __syncthreads();
    }
}

// ------------------------- KV3: kproj + norm/kn/threshold over vocab -------
// Tile = 64 rows. smem: W 128x132 + X 64x132.
#define KV3_SMEM ((128 * 132 + 64 * 132) * 4)

__global__ __launch_bounds__(256, 1)
void kv3(const float* __restrict__ kpw) {
    extern __shared__ float sm[];
    float* W = sm;                // 128 x 132
    float* X = sm + 128 * 132;    // 64 x 132

    const int tid = threadIdx.x;
    const int lane = tid & 31;
    const int w = tid >> 5;
    const int tg = w * 8;

    for (int i = tid; i < 128 * 32; i += 256) {
        int r = i >> 5, c = i & 31;
        *(float4*)(W + r * 132 + 4 * c) = *(const float4*)(kpw + r * 128 + 4 * c);
    }
    __syncthreads();

    const float4* W4 = (const float4*)W;
    const float4* X4 = (const float4*)X;

    for (int tile = blockIdx.x; tile < Vn / 64; tile += gridDim.x) {
        const int v0 = tile * 64;
        for (int i = tid; i < 64 * 32; i += 256) {
            int tk = i >> 5, q = i & 31;
            *(float4*)(X + tk * 132 + 4 * q) = *(const float4*)(g_hln + (size_t)(v0 + tk) * Hn + 4 * q);
        }
        __syncthreads();

        u64t acc[8][4];
#pragma unroll
        for (int i = 0; i < 8; ++i)
#pragma unroll
            for (int j = 0; j < 4; ++j) acc[i][j] = 0ull;

#pragma unroll 4
        for (int hh = 0; hh < 32; ++hh) {
            u64t wl[4], wh[4];
#pragma unroll
            for (int j = 0; j < 4; ++j) {
                float4 wq = W4[(lane + 32 * j) * 33 + hh];
                wl[j] = pk2(wq.x, wq.y);
                wh[j] = pk2(wq.z, wq.w);
            }
#pragma unroll
            for (int i = 0; i < 8; ++i) {
                float4 xq = X4[(tg + i) * 33 + hh];
                u64t xl = pk2(xq.x, xq.y), xh = pk2(xq.z, xq.w);
#pragma unroll
                for (int j = 0; j < 4; ++j) {
                    fma2(acc[i][j], xl, wl[j]);
                    fma2(acc[i][j], xh, wh[j]);
                }
            }
        }
#pragma unroll
        for (int i = 0; i < 8; ++i) {
            const size_t tok = (size_t)(v0 + tg + i);
            float kv[4];
            float s = 0.0f;
#pragma unroll
            for (int j = 0; j < 4; ++j) {
                kv[j] = hsum(acc[i][j]);
                g_Kv[tok * Hn + lane + 32 * j] = kv[j];
                s += kv[j] * kv[j];
            }
#pragma unroll
            for (int off = 16; off; off >>= 1) s += __shfl_xor_sync(0xffffffffu, s, off);
            float nm = fmaxf(sqrtf(s), 1e-12f);
#pragma unroll
            for (int j = 0; j < 4; ++j)
                g_KNv[tok * Hn + lane + 32 * j] = kv[j] / nm;
            if (lane == 0) g_THv[tok] = 0.16f * s;
        }
        __syncthreads();
    }
}

// ------------------------- KG: per-token gather ----------------------------
__global__ void kg(const void* __restrict__ seq) {
    const int lane = threadIdx.x & 31;
    const int w = threadIdx.x >> 5;
    const size_t t = (size_t)blockIdx.x * 8 + w;
    const int is64 = g_is64;
    const long long idx = is64 ? ((const long long*)seq)[t]
                               : (long long)((const int*)seq)[t];
    ((float4*)g_kall)[t * 32 + lane]  = ((const float4*)g_Kv)[(size_t)idx * 32 + lane];
    ((float4*)g_knall)[t * 32 + lane] = ((const float4*)g_KNv)[(size_t)idx * 32 + lane];
    if (lane == 0) g_thtok[t] = g_THv[idx];
}

// ------------------------- KG1: adjacent Gram g1[t] ------------------------
__global__ void kg1() {
    const int lane = threadIdx.x & 31;
    const int w = threadIdx.x >> 5;
    const size_t gt = (size_t)blockIdx.x * 8 + w;
    const int t = (int)(gt & (Ln - 1));
    if (t == 0 || t == Ln - 1) {
        if (lane == 0) g_g1[gt] = 0.0f;
        return;
    }
    float4 a = ((const float4*)g_knall)[(gt - 1) * 32 + lane];
    float4 c = ((const float4*)g_knall)[gt * 32 + lane];
    float s = a.x * c.x + a.y * c.y + a.z * c.z + a.w * c.w;
#pragma unroll
    for (int off = 16; off; off >>= 1) s += __shfl_xor_sync(0xffffffffu, s, off);
    if (lane == 0) g_g1[gt] = s;
}

// ------------------------- K2: lazy delta-rule scan ------------------------
// 64 CTAs x 256 threads. Thread pair (2r,2r+1) owns M row r (64 cols each,
// 32 f32x2 regs). At step t the main loop applies the step t-2 update fused
// with the matvec; the missing t-1 term is added exactly as s1*g1[t].
__global__ __launch_bounds__(256, 1)
void k2_scan() {
    const int b = blockIdx.x;
    const int tid = threadIdx.x;
    const int lane = tid & 31;
    const int w = tid >> 5;
    const int row = tid >> 1;
    const int half = tid & 1;
    const float* kb = g_kall + (size_t)b * Ln * Hn;
    const float* knb = g_knall + (size_t)b * Ln * Hn;

    __shared__ __align__(16) float kns[8][136];   // kn ring, slot = t & 7
    __shared__ __align__(16) float red[2][8];
    __shared__ float g1s[Ln];
    __shared__ float ths[Ln];

    for (int i = tid; i < Ln; i += 256) {
        g1s[i] = g_g1[b * Ln + i];
        ths[i] = g_thtok[(size_t)b * Ln + i];
    }
    for (int i = tid; i < 8 * 136; i += 256) ((float*)kns)[i] = 0.0f;
    __syncthreads();

    const int pos = 68 * (row >> 6) + (row & 63);  // bank-split kn layout
    if (half == 0) {
        kns[0][pos] = knb[row];
        kns[1][pos] = knb[Hn + row];
    }
    float Lprev = knb[2 * Hn + row];   // kn[2] in flight
    float kcur = kb[row];              // raw k_t for this row
    float knx1 = kb[Hn + row];

    u64t M[32];
#pragma unroll
    for (int c = 0; c < 32; ++c) M[c] = 0ull;

    float s1 = 0.0f, s2 = 0.0f, dprev = 0.0f, thprev = 0.0f;
    __syncthreads();

    for (int t = 0; t < Ln - 1; ++t) {
        // global prefetches (2+ steps ahead)
        const int tp = t + 3;
        float Lnew = 0.0f;
        if (tp < Ln - 1)       Lnew = knb[(size_t)tp * Hn + row];
        else if (tp == Ln - 1) Lnew = kb[(size_t)(Ln - 1) * Hn + row];  // q raw
        const int kp = t + 2;
        float knew = (kp <= Ln - 1) ? kb[(size_t)kp * Hn + row] : 0.0f;

        // ring store: kn[t+2] (loaded 2 iters ago)
        if (half == 0) kns[(t + 2) & 7][pos] = Lprev;
        __syncthreads();

        // fused: M += s_{t-2} * kn_{t-2}^T (row-scaled) ; vp_raw = M kn_t
        const float4* knT = (const float4*)(kns[t & 7] + 68 * half);
        const float4* knU = (const float4*)(kns[(t + 6) & 7] + 68 * half);
        const u64t s2p = pk2(s2, s2);
        u64t a0 = 0ull, a1 = 0ull;
#pragma unroll
        for (int cc = 0; cc < 16; ++cc) {
            float4 u = knU[cc], v = knT[cc];
            fma2(M[2 * cc],     s2p, pk2(u.x, u.y));
            fma2(M[2 * cc + 1], s2p, pk2(u.z, u.w));
            fma2(a0, M[2 * cc],     pk2(v.x, v.y));
            fma2(a1, M[2 * cc + 1], pk2(v.z, v.w));
        }

        // resolve fire_{t-1} (reduction finished last step)
        if (t > 0) {
            float4 r0 = *(const float4*)&red[(t + 1) & 1][0];
            float4 r1 = *(const float4*)&red[(t + 1) & 1][4];
            float dd = ((r0.x + r0.y) + (r0.z + r0.w)) + ((r1.x + r1.y) + (r1.z + r1.w));
            s1 = (dd >= thprev) ? dprev * (1.0f / 2048.0f) : 0.0f;
        } else {
            s1 = 0.0f;
        }
        s2 = s1;   // becomes the in-loop update next step

        float vph = hsum(a0) + hsum(a1);
        float vp = vph + __shfl_xor_sync(0xffffffffu, vph, 1);
        vp += s1 * g1s[t];             // exact missing-t-1 correction
        float d = kcur - vp;

        float dsq = d * d;             // both halves hold d -> 4-level tree
        dsq += __shfl_xor_sync(0xffffffffu, dsq, 2);
        dsq += __shfl_xor_sync(0xffffffffu, dsq, 4);
        dsq += __shfl_xor_sync(0xffffffffu, dsq, 8);
        dsq += __shfl_xor_sync(0xffffffffu, dsq, 16);
        if (lane == 0) red[t & 1][w] = dsq;

        dprev = d;
        thprev = ths[t];
        kcur = knx1;
        knx1 = knew;
        Lprev = Lnew;
    }

    // finalize: resolve fire_{2046}; apply s_{2045}, s_{2046}; read = M q
    __syncthreads();
    {
        float4 r0 = *(const float4*)&red[(Ln - 2) & 1][0];
        float4 r1 = *(const float4*)&red[(Ln - 2) & 1][4];
        float dd = ((r0.x + r0.y) + (r0.z + r0.w)) + ((r1.x + r1.y) + (r1.z + r1.w));
        float sF = (dd >= thprev) ? dprev * (1.0f / 2048.0f) : 0.0f;
        const u64t sAp = pk2(s2, s2);   // s_{2045}
        const u64t sFp = pk2(sF, sF);   // s_{2046}
        const float4* k5 = (const float4*)(kns[(Ln - 3) & 7] + 68 * half);
        const float4* k6 = (const float4*)(kns[(Ln - 2) & 7] + 68 * half);
        const float4* k7 = (const float4*)(kns[(Ln - 1) & 7] + 68 * half);  // q raw
        u64t a0 = 0ull, a1 = 0ull;
#pragma unroll
        for (int cc = 0; cc < 16; ++cc) {
            float4 u5 = k5[cc], u6 = k6[cc], q = k7[cc];
            fma2(M[2 * cc],     sAp, pk2(u5.x, u5.y));
            fma2(M[2 * cc + 1], sAp, pk2(u5.z, u5.w));
            fma2(M[2 * cc],     sFp, pk2(u6.x, u6.y));
            fma2(M[2 * cc + 1], sFp, pk2(u6.z, u6.w));
            fma2(a0, M[2 * cc],     pk2(q.x, q.y));
            fma2(a1, M[2 * cc + 1], pk2(q.z, q.w));
        }
        float vph = hsum(a0) + hsum(a1);
        float rd = vph + __shfl_xor_sync(0xffffffffu, vph, 1);
        if (half == 0) g_read[b * Hn + row] = rd;
    }
}

// ------------------------- K2b: r2 = read @ rp_w^T + rp_b ------------------
__global__ void k2b(const float* __restrict__ rpw, const float* __restrict__ rpb) {
    __shared__ __align__(16) float rs[128];
    const int b = blockIdx.x, tid = threadIdx.x;
    rs[tid] = g_read[b * Hn + tid];
    __syncthreads();
    const u64t* rp = (const u64t*)rs;
    u64t acc = 0ull;
#pragma unroll 8
    for (int j2 = 0; j2 < 64; ++j2) {
        u64t wv = *(const u64t*)(rpw + tid * 128 + 2 * j2);
        fma2(acc, rp[j2], wv);
    }
    g_r2[b * Hn + tid] = hsum(acc) + rpb[tid];
}

// ------------------------- K3: out = r2 @ out_w^T + out_b ------------------
#define K3_SMEM ((64 * 128 + 64 * 130) * 4)

__global__ __launch_bounds__(256, 1)
void k3(const float* __restrict__ ow, const float* __restrict__ ob,
        float* __restrict__ out) {
    extern __shared__ float sm[];
    float* r2s = sm;             // 64 x 128
    float* ws = sm + 64 * 128;   // 64 x 130

    const int tid = threadIdx.x;
    const int v0 = blockIdx.x * 64;

    for (int i = tid; i < 64 * 32; i += 256)
        ((float4*)r2s)[i] = ((const float4*)g_r2)[i];
    for (int i = tid; i < 64 * 64; i += 256) {
        int r = i >> 6, c = i & 63;
        *(float2*)(ws + r * 130 + 2 * c) = *(const float2*)(ow + (size_t)(v0 + r) * 128 + 2 * c);
    }
    __syncthreads();

    const int vl = tid & 63;
    const int bg = tid >> 6;
    const float obv = ob[v0 + vl];

#pragma unroll 4
    for (int bi = 0; bi < 16; ++bi) {
        int bb = bg * 16 + bi;
        u64t acc = 0ull;
#pragma unroll 16
        for (int h2 = 0; h2 < 64; ++h2)
            fma2(acc, *(const u64t*)(r2s + bb * 128 + 2 * h2),
                      *(const u64t*)(ws + vl * 130 + 2 * h2));
        out[(size_t)bb * Vn + v0 + vl] = hsum(acc) + obv;
    }
}

// ------------------------- launch ------------------------------------------
extern "C" void kernel_launch(void* const* d_in, const int* in_sizes, int n_in,
                              void* d_out, int out_size) {
    (void)in_sizes; (void)n_in; (void)out_size;
    const void*  seq = d_in[0];
    const float* ew  = (const float*)d_in[1];
    const float* w1  = (const float*)d_in[2];
    const float* b1  = (const float*)d_in[3];
    const float* w2  = (const float*)d_in[4];
    const float* b2  = (const float*)d_in[5];
    const float* lng = (const float*)d_in[6];
    const float* lnb = (const float*)d_in[7];
    const float* kpw = (const float*)d_in[8];
    const float* rpw = (const float*)d_in[9];
    const float* rpb = (const float*)d_in[10];
    const float* ow  = (const float*)d_in[11];
    const float* ob  = (const float*)d_in[12];
    float* out = (float*)d_out;

    cudaFuncSetAttribute(kv1, cudaFuncAttributeMaxDynamicSharedMemorySize, KV1_SMEM);
    cudaFuncSetAttribute(kv2, cudaFuncAttributeMaxDynamicSharedMemorySize, KV2_SMEM);
    cudaFuncSetAttribute(kv3, cudaFuncAttributeMaxDynamicSharedMemorySize, KV3_SMEM);
    cudaFuncSetAttribute(k3,  cudaFuncAttributeMaxDynamicSharedMemorySize, K3_SMEM);

    k0_detect<<<1, 256>>>((const unsigned int*)seq);
    kv1<<<148, 256, KV1_SMEM>>>(ew, w1, b1);
    kv2<<<148, 256, KV2_SMEM>>>(ew, w2, b2, lng, lnb);
    kv3<<<296, 256, KV3_SMEM>>>(kpw);
    kg <<<NTOK / 8, 256>>>(seq);
    kg1<<<NTOK / 8, 256>>>();
    k2_scan<<<Bn, 256>>>();
    k2b<<<Bn, 128>>>(rpw, rpb);
    k3<<<Vn / 64, 256, K3_SMEM>>>(ow, ob, out);
}